// round 10
// baseline (speedup 1.0000x reference)
#include <cuda_runtime.h>
#include <cuda_fp16.h>
#include <cstdint>
#include <math.h>

#define NHEADS 8
#define HC     32
#define HW     4096
#define CDIM   256
#define BDIM   8
#define LDIM   80

// ================= scratch =================
// conv weights, logical-linear lane-slot order:
// idx = ((((bN*16+cib)*9+tap)*2+wni)*32 + lane)*16 + ch*4 + e
__device__ uint32_t g_wh[2 * 16 * 9 * 2 * 32 * 16];
__device__ float    g_beta2[CDIM];
__device__ float    g_attn[BDIM * NHEADS * HW];
// U fragments, warp-coalesced chunks: [b][s(128)][wn_i(2)][chunk(3)][lane(32)][4]
__device__ uint32_t g_Uh2[BDIM * 128 * 2 * 384];
__device__ float    g_c[BDIM * NHEADS * LDIM];

__device__ __forceinline__ uint32_t pack_h2(float a, float b) {
    __half2 h = __floats2half2_rn(a, b);
    return *reinterpret_cast<uint32_t*>(&h);
}
__device__ __forceinline__ uint32_t smem_u32(const void* p) {
    uint32_t a;
    asm("{ .reg .u64 t; cvta.to.shared.u64 t, %1; cvt.u32.u64 %0, t; }" : "=r"(a) : "l"(p));
    return a;
}
__device__ __forceinline__ void cp_async16(uint32_t dst, const void* src) {
    asm volatile("cp.async.ca.shared.global [%0], [%1], 16;" :: "r"(dst), "l"(src));
}
#define CP_COMMIT() asm volatile("cp.async.commit_group;" ::: "memory")
#define CP_WAIT1()  asm volatile("cp.async.wait_group 1;" ::: "memory")
#define CP_WAIT0()  asm volatile("cp.async.wait_group 0;" ::: "memory")

__device__ __forceinline__ void mma_f16(float* c,
                                        uint32_t a0, uint32_t a1, uint32_t a2, uint32_t a3,
                                        uint32_t b0, uint32_t b1) {
    asm volatile(
        "mma.sync.aligned.m16n8k16.row.col.f32.f16.f16.f32 "
        "{%0,%1,%2,%3}, {%4,%5,%6,%7}, {%8,%9}, {%0,%1,%2,%3};"
        : "+f"(c[0]), "+f"(c[1]), "+f"(c[2]), "+f"(c[3])
        : "r"(a0), "r"(a1), "r"(a2), "r"(a3), "r"(b0), "r"(b1));
}

// ================= K0: conv weight prep (lane-slot fragment order, logical-linear) =================
__global__ void prep_kernel(const float* __restrict__ conv_w,
                            const float* __restrict__ gamma,
                            const float* __restrict__ beta,
                            const float* __restrict__ mean,
                            const float* __restrict__ var) {
    int idx = blockIdx.x * 256 + threadIdx.x;   // 294912 total
    if (idx < 2 * 16 * 9 * 2 * 32 * 16) {
        int e   = idx & 3;
        int ch  = (idx >> 2) & 3;
        int L   = (idx >> 4) & 31;
        int s2  = idx >> 9;
        int wni = s2 & 1;
        int s3  = s2 >> 1;
        int tap = s3 % 9;
        int s4  = s3 / 9;
        int cib = s4 & 15;
        int bN  = s4 >> 4;

        int t = L & 3, g = L >> 2;
        int half = ch >> 1;
        int nt   = (ch & 1) * 4 + e;
        int pair = t + 4 * half;
        int ci0  = cib * 16 + 2 * pair;
        int co   = bN * 128 + wni * 64 + nt * 8 + g;
        float inv = gamma[co] * rsqrtf(var[co] + 1e-3f);
        float w0 = conv_w[(co * CDIM + ci0) * 9 + tap] * inv;
        float w1 = conv_w[(co * CDIM + ci0 + 1) * 9 + tap] * inv;
        g_wh[idx] = pack_h2(w0, w1);
    }
    if (idx < CDIM) {
        float iv = gamma[idx] * rsqrtf(var[idx] + 1e-3f);
        g_beta2[idx] = beta[idx] - mean[idx] * iv;
    }
}

// ================= K0b: attn prep — U fragments, warp-coalesced chunks =================
__global__ void __launch_bounds__(256) prep_attn_kernel(
    const float* __restrict__ text,
    const float* __restrict__ proj_w,
    const float* __restrict__ proj_b,
    const float* __restrict__ attn_bias) {

    __shared__ float W_s[HC * 64];
    __shared__ float T_s[LDIM * 33];

    const int tid = threadIdx.x;
    const int b   = blockIdx.x;
    const int h   = blockIdx.y;
    const int ci0 = blockIdx.z * 64;
    const float invs = 0.17677669529663687f;

    for (int i = tid; i < HC * 64; i += 256) {
        int cc = i >> 6, cil = i & 63;
        W_s[i] = proj_w[(h * HC + cc) * CDIM + ci0 + cil];
    }
    for (int i = tid; i < LDIM * HC; i += 256) {
        int n = i >> 5, cc = i & 31;
        T_s[n * 33 + cc] = text[(b * LDIM + n) * CDIM + h * HC + cc];
    }
    __syncthreads();

    for (int i = tid; i < 32 * LDIM; i += 256) {
        int cp = i / LDIM, n = i % LDIM;
        float u0 = 0.f, u1 = 0.f;
        #pragma unroll
        for (int cc = 0; cc < HC; cc++) {
            float tv = T_s[n * 33 + cc];
            u0 += W_s[cc * 64 + 2 * cp]     * tv;
            u1 += W_s[cc * 64 + 2 * cp + 1] * tv;
        }
        int p    = blockIdx.z * 32 + cp;      // global ci-pair 0..127
        int s    = h * 16 + (p >> 3);
        int kp   = p & 7;
        int wn_i = n / 40;
        int rm   = n - wn_i * 40;
        int nt   = rm >> 3, gg = rm & 7;
        int half = kp >> 2, tt = kp & 3;
        int L    = gg * 4 + tt;
        int j    = half * 5 + nt;
        size_t dst = (((size_t)b * 128 + s) * 2 + wn_i) * 384 + (j >> 2) * 128 + L * 4 + (j & 3);
        g_Uh2[dst] = pack_h2(u0 * invs, u1 * invs);
    }
    if (blockIdx.z == 0 && tid < LDIM) {
        float cb = 0.f;
        #pragma unroll
        for (int cc = 0; cc < HC; cc++)
            cb += proj_b[h * HC + cc] * T_s[tid * 33 + cc];
        g_c[(b * NHEADS + h) * LDIM + tid] = cb * invs + attn_bias[h];
    }
}

// ================= K1: attn — fp16 mma, A resident, U via 3x LDG.128 =================
#define APS 136

__global__ void __launch_bounds__(256, 2) attn_mma_kernel(
    const float* __restrict__ img, const float* __restrict__ scale) {

    extern __shared__ __align__(16) uint32_t smA[];
    __shared__ float mxb[256];

    const int tid  = threadIdx.x;
    const int wid  = tid >> 5;
    const int lane = tid & 31;
    const int g    = lane >> 2;
    const int t    = lane & 3;

    const int b  = blockIdx.x >> 5;
    const int p0 = (blockIdx.x & 31) << 7;
    const int wm   = (wid & 3) * 32;
    const int wn_i = wid >> 2;
    const int wn   = wn_i * 40;

    const uint32_t* Ug = g_Uh2 + (size_t)b * 128 * 2 * 384;

    uint4 ub[2][3];
    auto load_u = [&](int s, int buf) {
        const uint32_t* base = Ug + ((size_t)s * 2 + wn_i) * 384 + lane * 4;
        ub[buf][0] = *reinterpret_cast<const uint4*>(base);
        ub[buf][1] = *reinterpret_cast<const uint4*>(base + 128);
        ub[buf][2] = *reinterpret_cast<const uint4*>(base + 256);
    };
    load_u(0, 0);

    // stage A: 128 ci-pairs x 128 px as half2
    const float* imgb = img + (size_t)b * CDIM * HW + p0;
    for (int i = tid; i < 128 * 128; i += 256) {
        int p = i >> 7, px = i & 127;
        smA[p * APS + px] = pack_h2(imgb[(2 * p) * HW + px], imgb[(2 * p + 1) * HW + px]);
    }
    __syncthreads();

    for (int h = 0; h < NHEADS; h++) {
        float c[2][5][4];
        #pragma unroll
        for (int mt = 0; mt < 2; mt++)
            #pragma unroll
            for (int nt = 0; nt < 5; nt++)
                #pragma unroll
                for (int i = 0; i < 4; i++) c[mt][nt][i] = 0.f;

        #pragma unroll 4
        for (int kk = 0; kk < 16; kk++) {
            const int s   = h * 16 + kk;
            const int cur = s & 1;
            if (s + 1 < 128) load_u(s + 1, cur ^ 1);

            uint32_t a[2][4];
            #pragma unroll
            for (int mt = 0; mt < 2; mt++) {
                const uint32_t* p = &smA[(kk * 8 + t) * APS + wm + mt * 16 + g];
                a[mt][0] = p[0];
                a[mt][1] = p[8];
                a[mt][2] = p[4 * APS];
                a[mt][3] = p[4 * APS + 8];
            }
            uint32_t bv[12];
            *reinterpret_cast<uint4*>(bv)     = ub[cur][0];
            *reinterpret_cast<uint4*>(bv + 4) = ub[cur][1];
            *reinterpret_cast<uint4*>(bv + 8) = ub[cur][2];
            #pragma unroll
            for (int nt = 0; nt < 5; nt++) {
                mma_f16(c[0][nt], a[0][0], a[0][1], a[0][2], a[0][3], bv[nt], bv[5 + nt]);
                mma_f16(c[1][nt], a[1][0], a[1][1], a[1][2], a[1][3], bv[nt], bv[5 + nt]);
            }
        }

        // epilogue: +c[n], max over tokens, sigmoid*scale
        float cn0[5], cn1[5];
        #pragma unroll
        for (int nt = 0; nt < 5; nt++) {
            int nn = wn + nt * 8 + 2 * t;
            cn0[nt] = g_c[(b * NHEADS + h) * LDIM + nn];
            cn1[nt] = g_c[(b * NHEADS + h) * LDIM + nn + 1];
        }
        #pragma unroll
        for (int mt = 0; mt < 2; mt++) {
            #pragma unroll
            for (int rr = 0; rr < 2; rr++) {
                float mx = -1e30f;
                #pragma unroll
                for (int nt = 0; nt < 5; nt++) {
                    mx = fmaxf(mx, fmaxf(c[mt][nt][rr * 2] + cn0[nt],
                                         c[mt][nt][rr * 2 + 1] + cn1[nt]));
                }
                mx = fmaxf(mx, __shfl_xor_sync(0xFFFFFFFF, mx, 1));
                mx = fmaxf(mx, __shfl_xor_sync(0xFFFFFFFF, mx, 2));
                if (t == 0)
                    mxb[wn_i * 128 + wm + mt * 16 + rr * 8 + g] = mx;
            }
        }
        __syncthreads();
        if (tid < 128) {
            float z = fmaxf(mxb[tid], mxb[128 + tid]);
            float a = (1.0f / (1.0f + expf(-z))) * scale[h];
            g_attn[((b * NHEADS + h) << 12) + p0 + tid] = a;
        }
        __syncthreads();
    }
}

// ================= K2: conv — fp16 mma, XOR-swizzled lane-slot weights =================
#define RAW_RS  70
#define RAW_PS  280
// smem (uint32): RAW0[2240] RAW1[2240] WS0[9216] WS1[9216]
#define CV_RAW0 0
#define CV_RAW1 2240
#define CV_WS0  4480
#define CV_WS1  (4480 + 9216)
#define CV_TOT  (4480 + 2 * 9216)

__global__ void __launch_bounds__(256, 2) conv_mma_kernel(
    const float* __restrict__ img, float* __restrict__ out) {

    extern __shared__ __align__(16) uint32_t sm[];
    __shared__ float b2s[128];
    const uint32_t sbase = smem_u32(sm);

    const int tid  = threadIdx.x;
    const int wid  = tid >> 5;
    const int lane = tid & 31;
    const int g    = lane >> 2;
    const int t    = lane & 3;
    const int swz  = (lane >> 1) & 3;

    const int bM = blockIdx.x;
    const int bN = blockIdx.y;
    const int b  = bM >> 5;
    const int y0 = (bM & 31) << 1;
    const int wm = (wid & 3) * 32;
    const int wn_i = wid >> 2;
    const int wn = wn_i * 64;

    const float*    imgb = img + (size_t)b * CDIM * HW;
    const uint32_t* wsrc = g_wh + (size_t)bN * 16 * 9216;

    if (tid < 128) b2s[tid] = g_beta2[bN * 128 + tid];

    auto stage_w = [&](int cib, int buf) {
        const uint32_t dstb = (uint32_t)(buf ? CV_WS1 : CV_WS0);
        #pragma unroll
        for (int it = 0; it < 9; it++) {
            int idx = tid + it * 256;            // 2304 chunks of 16B
            int row = idx >> 2;                  // 0..575 (= (tap*2+wni)*32 + lane)
            int ch  = idx & 3;
            uint32_t d = dstb + row * 16 + ((ch ^ ((row >> 1) & 3)) << 2);
            cp_async16(sbase + d * 4, wsrc + (size_t)cib * 9216 + (idx << 2));
        }
        CP_COMMIT();
    };
    auto stage_raw = [&](int cib, int buf) {
        uint32_t* dst = sm + (buf ? CV_RAW1 : CV_RAW0);
        for (int i = tid; i < 2112; i += 256) {
            int p  = i / 264;
            int r  = i % 264;
            int ry = r / 66, rx = r % 66;
            int gy = y0 - 1 + ry;
            int gx = rx - 1;
            float v0 = 0.f, v1 = 0.f;
            if ((unsigned)gy < 64u && (unsigned)gx < 64u) {
                const float* ip = imgb + (size_t)(cib * 16 + 2 * p) * HW + (gy << 6) + gx;
                v0 = ip[0];
                v1 = ip[HW];
            }
            dst[p * RAW_PS + ry * RAW_RS + rx] = pack_h2(v0, v1);
        }
    };

    float c[2][8][4];
    #pragma unroll
    for (int mt = 0; mt < 2; mt++)
        #pragma unroll
        for (int nt = 0; nt < 8; nt++)
            #pragma unroll
            for (int i = 0; i < 4; i++) c[mt][nt][i] = 0.f;

    // prolog
    stage_w(0, 0);
    stage_w(1, 1);
    stage_raw(0, 0);
    CP_WAIT1();
    __syncthreads();

    for (int cib = 0; cib < 16; cib++) {
        const int cur = cib & 1;
        const uint32_t* raw = sm + (cur ? CV_RAW1 : CV_RAW0);
        const uint32_t* wsm = sm + (cur ? CV_WS1  : CV_WS0);

        #pragma unroll
        for (int tap = 0; tap < 9; tap++) {
            const int ky = tap / 3, kx = tap % 3;

            uint32_t a[2][4];
            #pragma unroll
            for (int mt = 0; mt < 2; mt++) {
                int m    = wm + mt * 16 + g;
                int prow = m >> 6, pcol = m & 63;
                const uint32_t* p = &raw[t * RAW_PS + (prow + ky) * RAW_RS + (pcol + kx)];
                a[mt][0] = p[0];
                a[mt][1] = p[8];
                a[mt][2] = p[4 * RAW_PS];
                a[mt][3] = p[4 * RAW_PS + 8];
            }
            const uint4* wq = reinterpret_cast<const uint4*>(
                wsm + (tap * 2 + wn_i) * 512 + lane * 16);
            uint4 q0 = wq[swz];
            uint4 q1 = wq[1 ^ swz];
            uint4 q2 = wq[2 ^ swz];
            uint4 q3 = wq[3 ^ swz];
            uint32_t bv[16];
            *reinterpret_cast<uint4*>(bv)      = q0;
            *reinterpret_cast<uint4*>(bv + 4)  = q1;
            *reinterpret_cast<uint4*>(bv + 8)  = q2;
            *reinterpret_cast<uint4*>(bv + 12) = q3;
            #pragma unroll
            for (int nt = 0; nt < 8; nt++) {
                mma_f16(c[0][nt], a[0][0], a[0][1], a[0][2], a[0][3], bv[nt], bv[8 + nt]);
                mma_f16(c[1][nt], a[1][0], a[1][1], a[1][2], a[1][3], bv[nt], bv[8 + nt]);
            }
        }

        if (cib + 1 < 16) stage_raw(cib + 1, cur ^ 1);
        __syncthreads();                   // MMAs on cur done; raw(nxt) written
        if (cib + 2 < 16) {
            stage_w(cib + 2, cur);
            CP_WAIT1();
        } else if (cib + 1 < 16) {
            CP_WAIT0();
        }
        __syncthreads();                   // weights(cib+1) visible
    }

    // epilogue
    #pragma unroll
    for (int mt = 0; mt < 2; mt++) {
        #pragma unroll
        for (int rr = 0; rr < 2; rr++) {
            int m   = wm + mt * 16 + g + rr * 8;
            int pix = (y0 << 6) + m;
            #pragma unroll
            for (int nt = 0; nt < 8; nt++) {
                int co = bN * 128 + wn + nt * 8 + 2 * t;
                float gate = g_attn[((b * NHEADS + (co >> 5)) << 12) + pix];
                float v0 = c[mt][nt][rr * 2 + 0] + b2s[wn + nt * 8 + 2 * t];
                float v1 = c[mt][nt][rr * 2 + 1] + b2s[wn + nt * 8 + 2 * t + 1];
                out[(((size_t)b * CDIM + co) << 12) + pix]     = v0 * gate;
                out[(((size_t)b * CDIM + co + 1) << 12) + pix] = v1 * gate;
            }
        }
    }
}

// ================= launch =================
extern "C" void kernel_launch(void* const* d_in, const int* in_sizes, int n_in,
                              void* d_out, int out_size) {
    const float* img_feat   = (const float*)d_in[0];
    const float* text_feats = (const float*)d_in[1];
    const float* proj_w     = (const float*)d_in[2];
    const float* proj_b     = (const float*)d_in[3];
    const float* attn_bias  = (const float*)d_in[4];
    const float* scale      = (const float*)d_in[5];
    const float* conv_w     = (const float*)d_in[6];
    const float* bn_gamma   = (const float*)d_in[7];
    const float* bn_beta    = (const float*)d_in[8];
    const float* bn_mean    = (const float*)d_in[9];
    const float* bn_var     = (const float*)d_in[10];
    float* out = (float*)d_out;

    static int attr_set = 0;
    if (!attr_set) {
        cudaFuncSetAttribute(attn_mma_kernel,
                             cudaFuncAttributeMaxDynamicSharedMemorySize, 128 * APS * 4);
        cudaFuncSetAttribute(conv_mma_kernel,
                             cudaFuncAttributeMaxDynamicSharedMemorySize, CV_TOT * 4);
        attr_set = 1;
    }

    prep_kernel<<<1152, 256>>>(conv_w, bn_gamma, bn_beta, bn_mean, bn_var);

    dim3 gp(BDIM, NHEADS, 4);
    prep_attn_kernel<<<gp, 256>>>(text_feats, proj_w, proj_b, attn_bias);

    attn_mma_kernel<<<BDIM * 32, 256, 128 * APS * 4>>>(img_feat, scale);

    dim3 g2(256, 2);
    conv_mma_kernel<<<g2, 256, CV_TOT * 4>>>(img_feat, out);
}

// round 11
// speedup vs baseline: 1.0980x; 1.0980x over previous
#include <cuda_runtime.h>
#include <cuda_fp16.h>
#include <cstdint>
#include <math.h>

#define NHEADS 8
#define HC     32
#define HW     4096
#define CDIM   256
#define BDIM   8
#define LDIM   80

// ================= scratch =================
// conv weights as half2 (ci-pairs): [bN][cib16][tap][kp][co]
__device__ uint32_t g_wh[2 * 16 * 72 * 128];
__device__ float    g_beta2[CDIM];
__device__ float    g_attn[BDIM * NHEADS * HW];
// U as half2 (ci-pairs): [b][h*16+kk][kp][n(80)]
__device__ uint32_t g_Uh[BDIM * 128 * 8 * 80];
__device__ float    g_c[BDIM * NHEADS * LDIM];
// padded half2 image: [b][pair(128)][yp(66)][xp(72)]; border zeros baked in
__device__ uint32_t g_imgp[BDIM * 128 * 66 * 72];

__device__ __forceinline__ uint32_t pack_h2(float a, float b) {
    __half2 h = __floats2half2_rn(a, b);
    return *reinterpret_cast<uint32_t*>(&h);
}
__device__ __forceinline__ uint32_t smem_u32(const void* p) {
    uint32_t a;
    asm("{ .reg .u64 t; cvta.to.shared.u64 t, %1; cvt.u32.u64 %0, t; }" : "=r"(a) : "l"(p));
    return a;
}
__device__ __forceinline__ void cp_async16(uint32_t dst, const void* src) {
    asm volatile("cp.async.ca.shared.global [%0], [%1], 16;" :: "r"(dst), "l"(src));
}
#define CP_COMMIT() asm volatile("cp.async.commit_group;" ::: "memory")
#define CP_WAIT1()  asm volatile("cp.async.wait_group 1;" ::: "memory")
#define CP_WAIT0()  asm volatile("cp.async.wait_group 0;" ::: "memory")

__device__ __forceinline__ void mma_f16(float* c,
                                        uint32_t a0, uint32_t a1, uint32_t a2, uint32_t a3,
                                        uint32_t b0, uint32_t b1) {
    asm volatile(
        "mma.sync.aligned.m16n8k16.row.col.f32.f16.f16.f32 "
        "{%0,%1,%2,%3}, {%4,%5,%6,%7}, {%8,%9}, {%0,%1,%2,%3};"
        : "+f"(c[0]), "+f"(c[1]), "+f"(c[2]), "+f"(c[3])
        : "r"(a0), "r"(a1), "r"(a2), "r"(a3), "r"(b0), "r"(b1));
}

// ================= K0a: image convert + pad (fp32 -> half2 ci-pairs) =================
__global__ void prep_img_kernel(const float* __restrict__ img) {
    int idx = blockIdx.x * 256 + threadIdx.x;            // 4,866,048 total
    if (idx >= BDIM * 128 * 66 * 72) return;
    int xp = idx % 72;
    int r  = idx / 72;
    int yp = r % 66;
    int p  = (r / 66) & 127;
    int b  = r / (66 * 128);
    uint32_t v = 0;
    if (xp >= 1 && xp <= 64 && yp >= 1 && yp <= 64) {
        const float* ip = img + ((size_t)b * CDIM + 2 * p) * HW + ((yp - 1) << 6) + (xp - 1);
        v = pack_h2(ip[0], ip[HW]);
    }
    g_imgp[idx] = v;
}

// ================= K0b: conv weight prep (half2 ci-pairs, co-coalesced) =================
__global__ void prep_kernel(const float* __restrict__ conv_w,
                            const float* __restrict__ gamma,
                            const float* __restrict__ beta,
                            const float* __restrict__ mean,
                            const float* __restrict__ var) {
    int idx = blockIdx.x * 256 + threadIdx.x;
    if (idx < 2 * 16 * 72 * 128) {
        int co  = idx & 127;
        int r   = idx >> 7;
        int kp  = r & 7;   r >>= 3;
        int tap = r % 9;   r /= 9;
        int cib = r & 15;
        int bN  = r >> 4;
        int ci0 = cib * 16 + 2 * kp;
        int cog = bN * 128 + co;
        float inv = gamma[cog] * rsqrtf(var[cog] + 1e-3f);
        float w0 = conv_w[(cog * CDIM + ci0) * 9 + tap] * inv;
        float w1 = conv_w[(cog * CDIM + ci0 + 1) * 9 + tap] * inv;
        g_wh[idx] = pack_h2(w0, w1);
    }
    if (idx < CDIM) {
        float iv = gamma[idx] * rsqrtf(var[idx] + 1e-3f);
        g_beta2[idx] = beta[idx] - mean[idx] * iv;
    }
}

// ================= K0c: attn prep — U half2 pairs, grid (B, H, 4) =================
__global__ void __launch_bounds__(256) prep_attn_kernel(
    const float* __restrict__ text,
    const float* __restrict__ proj_w,
    const float* __restrict__ proj_b,
    const float* __restrict__ attn_bias) {

    __shared__ float W_s[HC * 64];
    __shared__ float T_s[LDIM * 33];

    const int tid = threadIdx.x;
    const int b   = blockIdx.x;
    const int h   = blockIdx.y;
    const int ci0 = blockIdx.z * 64;
    const float invs = 0.17677669529663687f;

    for (int i = tid; i < HC * 64; i += 256) {
        int cc = i >> 6, cil = i & 63;
        W_s[i] = proj_w[(h * HC + cc) * CDIM + ci0 + cil];
    }
    for (int i = tid; i < LDIM * HC; i += 256) {
        int n = i >> 5, cc = i & 31;
        T_s[n * 33 + cc] = text[(b * LDIM + n) * CDIM + h * HC + cc];
    }
    __syncthreads();

    for (int i = tid; i < 32 * LDIM; i += 256) {
        int cp = i / LDIM, n = i % LDIM;
        float u0 = 0.f, u1 = 0.f;
        #pragma unroll
        for (int cc = 0; cc < HC; cc++) {
            float tv = T_s[n * 33 + cc];
            u0 += W_s[cc * 64 + 2 * cp]     * tv;
            u1 += W_s[cc * 64 + 2 * cp + 1] * tv;
        }
        int p  = blockIdx.z * 32 + cp;
        int kk = p >> 3, kp = p & 7;
        int s  = h * 16 + kk;
        g_Uh[((size_t)(b * 128 + s) * 8 + kp) * 80 + n] = pack_h2(u0 * invs, u1 * invs);
    }
    if (blockIdx.z == 0 && tid < LDIM) {
        float cb = 0.f;
        #pragma unroll
        for (int cc = 0; cc < HC; cc++)
            cb += proj_b[h * HC + cc] * T_s[tid * 33 + cc];
        g_c[(b * NHEADS + h) * LDIM + tid] = cb * invs + attn_bias[h];
    }
}

// ================= K1: attn — fp16 mma, A staged via cp.async from padded image =================
#define A_PS 152    // per-pair stride: 24 mod 32 -> banks 24t+g distinct
#define A_RS2 72

__global__ void __launch_bounds__(256, 2) attn_mma_kernel(const float* __restrict__ scale) {

    extern __shared__ __align__(16) uint32_t smA[];   // 128 pairs * A_PS
    __shared__ float mxb[256];

    const int tid  = threadIdx.x;
    const int wid  = tid >> 5;
    const int lane = tid & 31;
    const int g    = lane >> 2;
    const int t    = lane & 3;

    const int b   = blockIdx.x >> 5;
    const int y0a = (blockIdx.x & 31) << 1;    // 2 image rows
    const int p0  = y0a << 6;
    const int wm   = (wid & 3) * 32;
    const int wn_i = wid >> 2;
    const int wn   = wn_i * 40;

    const uint32_t sbase = smem_u32(smA);
    const uint32_t* Ug = g_Uh + (size_t)(b * 128) * 8 * 80;
    int n0[5];
    #pragma unroll
    for (int nt = 0; nt < 5; nt++) n0[nt] = wn + nt * 8 + g;

    uint32_t ub[2][5][2];
    auto load_u = [&](int s, int buf) {
        const uint32_t* base = Ug + (size_t)s * 640;
        #pragma unroll
        for (int nt = 0; nt < 5; nt++) {
            ub[buf][nt][0] = base[t * 80 + n0[nt]];
            ub[buf][nt][1] = base[(t + 4) * 80 + n0[nt]];
        }
    };
    load_u(0, 0);

    // stage A via cp.async: 128 pairs x 2 padded rows (y0a+1, y0a+2), full 72-wide rows
    {
        const uint32_t* src0 = g_imgp + ((size_t)(b * 128) * 66 + y0a + 1) * 72;
        #pragma unroll
        for (int it = 0; it < 18; it++) {
            int idx = tid + it * 256;            // 4608 chunks
            int p  = idx / 36;
            int r  = idx % 36;
            int ry = r / 18, ch = r % 18;
            cp_async16(sbase + (uint32_t)((p * A_PS + ry * A_RS2 + ch * 4) * 4),
                       src0 + (size_t)p * 66 * 72 + ry * 72 + ch * 4);
        }
        CP_COMMIT();
        CP_WAIT0();
    }
    __syncthreads();

    for (int h = 0; h < NHEADS; h++) {
        float c[2][5][4];
        #pragma unroll
        for (int mt = 0; mt < 2; mt++)
            #pragma unroll
            for (int nt = 0; nt < 5; nt++)
                #pragma unroll
                for (int i = 0; i < 4; i++) c[mt][nt][i] = 0.f;

        #pragma unroll 4
        for (int kk = 0; kk < 16; kk++) {
            const int s   = h * 16 + kk;
            const int cur = s & 1;
            if (s + 1 < 128) load_u(s + 1, cur ^ 1);

            uint32_t a[2][4];
            #pragma unroll
            for (int mt = 0; mt < 2; mt++) {
                int m    = wm + mt * 16 + g;
                int prow = m >> 6, pcol = m & 63;
                const uint32_t* p = &smA[(kk * 8 + t) * A_PS + prow * A_RS2 + 1 + pcol];
                a[mt][0] = p[0];
                a[mt][1] = p[8];
                a[mt][2] = p[4 * A_PS];
                a[mt][3] = p[4 * A_PS + 8];
            }
            #pragma unroll
            for (int nt = 0; nt < 5; nt++) {
                mma_f16(c[0][nt], a[0][0], a[0][1], a[0][2], a[0][3],
                        ub[cur][nt][0], ub[cur][nt][1]);
                mma_f16(c[1][nt], a[1][0], a[1][1], a[1][2], a[1][3],
                        ub[cur][nt][0], ub[cur][nt][1]);
            }
        }

        float cn0[5], cn1[5];
        #pragma unroll
        for (int nt = 0; nt < 5; nt++) {
            int nn = wn + nt * 8 + 2 * t;
            cn0[nt] = g_c[(b * NHEADS + h) * LDIM + nn];
            cn1[nt] = g_c[(b * NHEADS + h) * LDIM + nn + 1];
        }
        #pragma unroll
        for (int mt = 0; mt < 2; mt++) {
            #pragma unroll
            for (int rr = 0; rr < 2; rr++) {
                float mx = -1e30f;
                #pragma unroll
                for (int nt = 0; nt < 5; nt++) {
                    mx = fmaxf(mx, fmaxf(c[mt][nt][rr * 2] + cn0[nt],
                                         c[mt][nt][rr * 2 + 1] + cn1[nt]));
                }
                mx = fmaxf(mx, __shfl_xor_sync(0xFFFFFFFF, mx, 1));
                mx = fmaxf(mx, __shfl_xor_sync(0xFFFFFFFF, mx, 2));
                if (t == 0)
                    mxb[wn_i * 128 + wm + mt * 16 + rr * 8 + g] = mx;
            }
        }
        __syncthreads();
        if (tid < 128) {
            float z = fmaxf(mxb[tid], mxb[128 + tid]);
            float a = (1.0f / (1.0f + expf(-z))) * scale[h];
            g_attn[((b * NHEADS + h) << 12) + p0 + tid] = a;
        }
        __syncthreads();
    }
}

// ================= K2: conv — fp16 mma, fully cp.async staged =================
#define RAW_RS  72      // padded row stride (u32)
#define RAW_PS  296     // per-pair stride: 8 mod 32 -> banks 8t+g distinct
#define WCO     136     // weight co stride: conflict-free (banks 8t+g)
// smem (u32): RAW0[2368] RAW1[2368] WS0[9792] WS1[9792]
#define CV_RAW0 0
#define CV_RAW1 2368
#define CV_WS0  4736
#define CV_WS1  (4736 + 9792)
#define CV_TOT  (4736 + 2 * 9792)

__global__ void __launch_bounds__(256, 2) conv_mma_kernel(float* __restrict__ out) {

    extern __shared__ __align__(16) uint32_t sm[];
    __shared__ float b2s[128];
    const uint32_t sbase = smem_u32(sm);

    const int tid  = threadIdx.x;
    const int wid  = tid >> 5;
    const int lane = tid & 31;
    const int g    = lane >> 2;
    const int t    = lane & 3;

    const int bM = blockIdx.x;
    const int bN = blockIdx.y;
    const int b  = bM >> 5;
    const int y0 = (bM & 31) << 1;
    const int wm = (wid & 3) * 32;
    const int wn = (wid >> 2) * 64;

    const uint32_t* imgp = g_imgp + (size_t)(b * 128) * 66 * 72;
    const uint32_t* wsrc = g_wh + (size_t)bN * 16 * 9216;

    if (tid < 128) b2s[tid] = g_beta2[bN * 128 + tid];

    auto stage_w = [&](int cib, int buf) {
        const uint32_t dst = sbase + (uint32_t)((buf ? CV_WS1 : CV_WS0) * 4);
        #pragma unroll
        for (int it = 0; it < 9; it++) {
            int idx = tid + it * 256;            // 2304 chunks
            int row = idx >> 5;                  // 0..71 = tap*8+kp
            int ch  = idx & 31;
            cp_async16(dst + (uint32_t)((row * WCO + ch * 4) * 4),
                       wsrc + (size_t)cib * 9216 + (idx << 2));
        }
        CP_COMMIT();
    };
    auto stage_raw = [&](int cib, int buf) {
        const uint32_t dst = sbase + (uint32_t)((buf ? CV_RAW1 : CV_RAW0) * 4);
        const uint32_t* src0 = imgp + ((size_t)(cib * 8) * 66 + y0) * 72;
        #pragma unroll
        for (int it = 0; it < 3; it++) {
            int idx = tid + it * 256;            // 576 chunks: 8 pairs x 4 rows x 18
            if (idx < 576) {
                int p  = idx / 72;
                int r  = idx % 72;
                int ry = r / 18, ch = r % 18;
                cp_async16(dst + (uint32_t)((p * RAW_PS + ry * RAW_RS + ch * 4) * 4),
                           src0 + (size_t)p * 66 * 72 + ry * 72 + ch * 4);
            }
        }
        CP_COMMIT();
    };

    float c[2][8][4];
    #pragma unroll
    for (int mt = 0; mt < 2; mt++)
        #pragma unroll
        for (int nt = 0; nt < 8; nt++)
            #pragma unroll
            for (int i = 0; i < 4; i++) c[mt][nt][i] = 0.f;

    // prolog: commit order raw(0), w(0), w(1); wait leaves w(1) pending
    stage_raw(0, 0);
    stage_w(0, 0);
    stage_w(1, 1);
    CP_WAIT1();
    __syncthreads();

    for (int cib = 0; cib < 16; cib++) {
        const int cur = cib & 1;
        if (cib + 1 < 16) stage_raw(cib + 1, cur ^ 1);   // async into other buffer

        const uint32_t* raw = sm + (cur ? CV_RAW1 : CV_RAW0);
        const uint32_t* wsm = sm + (cur ? CV_WS1  : CV_WS0);

        #pragma unroll
        for (int tap = 0; tap < 9; tap++) {
            const int ky = tap / 3, kx = tap % 3;

            uint32_t a[2][4];
            #pragma unroll
            for (int mt = 0; mt < 2; mt++) {
                int m    = wm + mt * 16 + g;
                int prow = m >> 6, pcol = m & 63;
                const uint32_t* p = &raw[t * RAW_PS + (prow + ky) * RAW_RS + pcol + kx];
                a[mt][0] = p[0];
                a[mt][1] = p[8];
                a[mt][2] = p[4 * RAW_PS];
                a[mt][3] = p[4 * RAW_PS + 8];
            }
            const uint32_t* w0 = &wsm[(tap * 8 + t) * WCO + wn + g];
            const uint32_t* w1 = &wsm[(tap * 8 + t + 4) * WCO + wn + g];
            #pragma unroll
            for (int nt = 0; nt < 8; nt++) {
                uint32_t b0 = w0[nt * 8];
                uint32_t b1 = w1[nt * 8];
                mma_f16(c[0][nt], a[0][0], a[0][1], a[0][2], a[0][3], b0, b1);
                mma_f16(c[1][nt], a[1][0], a[1][1], a[1][2], a[1][3], b0, b1);
            }
        }

        __syncthreads();                   // done reading cur raw+weights
        if (cib + 2 < 16) {
            stage_w(cib + 2, cur);
            CP_WAIT1();                    // completes w(cib+1), raw(cib+1)
        } else if (cib + 1 < 16) {
            CP_WAIT0();
        }
        __syncthreads();                   // next buffers visible
    }

    // epilogue
    #pragma unroll
    for (int mt = 0; mt < 2; mt++) {
        #pragma unroll
        for (int rr = 0; rr < 2; rr++) {
            int m   = wm + mt * 16 + g + rr * 8;
            int pix = (y0 << 6) + m;
            #pragma unroll
            for (int nt = 0; nt < 8; nt++) {
                int co = bN * 128 + wn + nt * 8 + 2 * t;
                float gate = g_attn[((b * NHEADS + (co >> 5)) << 12) + pix];
                float v0 = c[mt][nt][rr * 2 + 0] + b2s[wn + nt * 8 + 2 * t];
                float v1 = c[mt][nt][rr * 2 + 1] + b2s[wn + nt * 8 + 2 * t + 1];
                out[(((size_t)b * CDIM + co) << 12) + pix]     = v0 * gate;
                out[(((size_t)b * CDIM + co + 1) << 12) + pix] = v1 * gate;
            }
        }
    }
}

// ================= launch =================
extern "C" void kernel_launch(void* const* d_in, const int* in_sizes, int n_in,
                              void* d_out, int out_size) {
    const float* img_feat   = (const float*)d_in[0];
    const float* text_feats = (const float*)d_in[1];
    const float* proj_w     = (const float*)d_in[2];
    const float* proj_b     = (const float*)d_in[3];
    const float* attn_bias  = (const float*)d_in[4];
    const float* scale      = (const float*)d_in[5];
    const float* conv_w     = (const float*)d_in[6];
    const float* bn_gamma   = (const float*)d_in[7];
    const float* bn_beta    = (const float*)d_in[8];
    const float* bn_mean    = (const float*)d_in[9];
    const float* bn_var     = (const float*)d_in[10];
    float* out = (float*)d_out;

    static int attr_set = 0;
    if (!attr_set) {
        cudaFuncSetAttribute(attn_mma_kernel,
                             cudaFuncAttributeMaxDynamicSharedMemorySize, 128 * A_PS * 4);
        cudaFuncSetAttribute(conv_mma_kernel,
                             cudaFuncAttributeMaxDynamicSharedMemorySize, CV_TOT * 4);
        attr_set = 1;
    }

    prep_img_kernel<<<(BDIM * 128 * 66 * 72 + 255) / 256, 256>>>(img_feat);
    prep_kernel<<<1152, 256>>>(conv_w, bn_gamma, bn_beta, bn_mean, bn_var);

    dim3 gp(BDIM, NHEADS, 4);
    prep_attn_kernel<<<gp, 256>>>(text_feats, proj_w, proj_b, attn_bias);

    attn_mma_kernel<<<BDIM * 32, 256, 128 * A_PS * 4>>>(scale);

    dim3 g2(256, 2);
    conv_mma_kernel<<<g2, 256, CV_TOT * 4>>>(out);
}